// round 5
// baseline (speedup 1.0000x reference)
#include <cuda_runtime.h>

// Problem constants
#define HH   224
#define WW   224
#define CC   3
#define SS   17          // 1 zero angle + 16 sampled
#define NN   32
#define TILE 32          // output tile is TILE x TILE
#define NTX  7           // 224/32 tiles per axis
#define SMW  48          // max rotated-bbox extent for 32x32 tile @ |theta|<=30deg (43.7+margin)
#define SMP  49          // padded stride (bank-conflict mitigation)
#define PLANE (HH*WW)    // 50176

__global__ __launch_bounds__(256)
void rot_bilinear_kernel(const float* __restrict__ x,
                         const float* __restrict__ thetas,
                         float* __restrict__ out)
{
    __shared__ float sm[CC][SMW][SMP];

    const int tile  = blockIdx.x;           // 0..48
    const int s_idx = blockIdx.y;           // 0..16
    const int n     = blockIdx.z;           // 0..31
    const int th0   = (tile / NTX) * TILE;  // tile origin (h)
    const int tw0   = (tile % NTX) * TILE;  // tile origin (w)
    const int tid   = threadIdx.x;

    const float theta = __ldg(&thetas[n * SS + s_idx]);
    float st, ct;
    sincosf(theta, &st, &ct);

    // Input-pixel coords: ix = ct*X - st*Y + 111.5 ; iy = st*X + ct*Y + 111.5
    // with X = w - 111.5, Y = h - 111.5  (algebraically identical to the
    // reference's normalized-grid formulation).
    const float Xlo = (float)tw0 - 111.5f, Xhi = Xlo + (float)(TILE - 1);
    const float Ylo = (float)th0 - 111.5f, Yhi = Ylo + (float)(TILE - 1);

    // bbox of sample coords over the tile (linear map -> extremes at corners)
    float c00 = ct * Xlo - st * Ylo, c01 = ct * Xlo - st * Yhi;
    float c10 = ct * Xhi - st * Ylo, c11 = ct * Xhi - st * Yhi;
    float ixmin = fminf(fminf(c00, c01), fminf(c10, c11)) + 111.5f - 0.01f;
    float ixmax = fmaxf(fmaxf(c00, c01), fmaxf(c10, c11)) + 111.5f + 0.01f;
    float d00 = st * Xlo + ct * Ylo, d01 = st * Xlo + ct * Yhi;
    float d10 = st * Xhi + ct * Ylo, d11 = st * Xhi + ct * Yhi;
    float iymin = fminf(fminf(d00, d01), fminf(d10, d11)) + 111.5f - 0.01f;
    float iymax = fmaxf(fmaxf(d00, d01), fmaxf(d10, d11)) + 111.5f + 0.01f;

    // intersect bbox (expanded +1 for the bilinear right/bottom tap) with image
    int x0 = max(0, min(WW - 1, (int)floorf(ixmin)));
    int x1 = max(0, min(WW - 1, (int)floorf(ixmax) + 1));
    int y0 = max(0, min(HH - 1, (int)floorf(iymin)));
    int y1 = max(0, min(HH - 1, (int)floorf(iymax) + 1));
    int bw = min(SMW, max(1, x1 - x0 + 1));
    int bh = min(SMW, max(1, y1 - y0 + 1));

    // Cooperative load of the (clamped) bbox region, all 3 channels.
    // Rows are contiguous in gmem -> coalesced.
    {
        const float* img = x + (size_t)n * (CC * PLANE);
        const int per_ch = bh * bw;
        const int total  = CC * per_ch;
        for (int i = tid; i < total; i += 256) {
            int ch  = i / per_ch;
            int rem = i - ch * per_ch;
            int r   = rem / bw;
            int col = rem - r * bw;
            sm[ch][r][col] = img[ch * PLANE + (y0 + r) * WW + (x0 + col)];
        }
    }
    __syncthreads();

    float* outp = out + ((size_t)(n * SS + s_idx) * CC) * PLANE;

    #pragma unroll
    for (int k = 0; k < 4; k++) {
        const int p  = tid + k * 256;       // 0..1023 within tile
        const int hh = th0 + (p >> 5);
        const int ww = tw0 + (p & 31);

        const float Xf = (float)ww - 111.5f;
        const float Yf = (float)hh - 111.5f;
        const float ix = fmaf(ct, Xf, fmaf(-st, Yf, 111.5f));
        const float iy = fmaf(st, Xf, fmaf( ct, Yf, 111.5f));

        const float fx0 = floorf(ix);
        const float fy0 = floorf(iy);
        const float wx1 = ix - fx0;
        const float wy1 = iy - fy0;
        const float wx0 = 1.0f - wx1;
        const float wy0 = 1.0f - wy1;

        const int ix0 = (int)fx0;
        const int iy0 = (int)fy0;
        const int ix1 = ix0 + 1;
        const int iy1 = iy0 + 1;

        const float vx0 = ((unsigned)ix0 < (unsigned)WW) ? 1.0f : 0.0f;
        const float vx1 = ((unsigned)ix1 < (unsigned)WW) ? 1.0f : 0.0f;
        const float vy0 = ((unsigned)iy0 < (unsigned)HH) ? 1.0f : 0.0f;
        const float vy1 = ((unsigned)iy1 < (unsigned)HH) ? 1.0f : 0.0f;

        const float w00 = wy0 * wx0 * (vy0 * vx0);
        const float w01 = wy0 * wx1 * (vy0 * vx1);
        const float w10 = wy1 * wx0 * (vy1 * vx0);
        const float w11 = wy1 * wx1 * (vy1 * vx1);

        // smem-relative tap indices; valid taps are guaranteed inside the
        // region by construction, invalid taps contribute weight 0 (clamp is
        // only OOB safety).
        const int sx0 = min(max(ix0 - x0, 0), bw - 1);
        const int sx1 = min(max(ix1 - x0, 0), bw - 1);
        const int sy0 = min(max(iy0 - y0, 0), bh - 1);
        const int sy1 = min(max(iy1 - y0, 0), bh - 1);

        const int off = hh * WW + ww;
        #pragma unroll
        for (int ch = 0; ch < CC; ch++) {
            float v = w00 * sm[ch][sy0][sx0] + w01 * sm[ch][sy0][sx1]
                    + w10 * sm[ch][sy1][sx0] + w11 * sm[ch][sy1][sx1];
            outp[ch * PLANE + off] = v;
        }
    }
}

extern "C" void kernel_launch(void* const* d_in, const int* in_sizes, int n_in,
                              void* d_out, int out_size)
{
    const float* x      = (const float*)d_in[0];   // (32,3,224,224)
    const float* thetas = (const float*)d_in[1];   // (32,17)
    float* out          = (float*)d_out;           // (32,17,3,224,224)

    dim3 grid(NTX * NTX, SS, NN);  // (49, 17, 32)
    rot_bilinear_kernel<<<grid, 256>>>(x, thetas, out);
}